// round 1
// baseline (speedup 1.0000x reference)
#include <cuda_runtime.h>
#include <math.h>

// Problem constants
#define TOK   2048          // B*S tokens
#define HD    1024          // hidden dim H
#define ID    1024          // intermediate I
#define NE    32            // experts
#define TOPK  4
#define TWOI  2048          // 2*I
#define PAIRS (TOK*TOPK)    // 8192 (token, expert) pairs
#define LIMITF 7.0f
#define ALPHAF 1.702f

// -------- device scratch (no allocs allowed) --------
__device__ int   g_count[NE];
__device__ int   g_offset[NE];
__device__ int   g_cursor[NE];
__device__ int   g_topk_idx[TOK * TOPK];
__device__ float g_topk_w[TOK * TOPK];
__device__ int   g_pair_token[PAIRS];
__device__ int   g_pair_e[PAIRS];
__device__ int   g_pair_of[TOK * TOPK];
__device__ float g_C[(size_t)PAIRS * TWOI];   // gate_up GEMM output (64 MB)
__device__ float g_act[(size_t)PAIRS * ID];   // activated intermediate (32 MB)
__device__ float g_y[(size_t)PAIRS * HD];     // down GEMM output (32 MB)

// -------- K0: reset counters --------
__global__ void reset_kernel() {
    int i = threadIdx.x;
    if (i < NE) g_count[i] = 0;
}

// -------- K1: router (one block per token) --------
__global__ void router_kernel(const float* __restrict__ x,
                              const float* __restrict__ rw,
                              const float* __restrict__ rb,
                              float* __restrict__ scores_out) {
    const int t    = blockIdx.x;
    const int tid  = threadIdx.x;
    const int warp = tid >> 5;
    const int lane = tid & 31;

    __shared__ float logits[NE];
    const float* xr = x + (size_t)t * HD;

    // 8 warps, 4 experts each
    for (int e = warp; e < NE; e += 8) {
        const float* w = rw + (size_t)e * HD;
        float s = 0.f;
        for (int h = lane; h < HD; h += 32) s += xr[h] * w[h];
        #pragma unroll
        for (int off = 16; off; off >>= 1) s += __shfl_down_sync(0xffffffffu, s, off);
        if (lane == 0) logits[e] = s + rb[e];
    }
    __syncthreads();

    if (warp == 0) {
        float cur = logits[lane];
        float sel_val[TOPK];
        int   sel_idx[TOPK];
        #pragma unroll
        for (int k = 0; k < TOPK; k++) {
            float bv = cur; int bi = lane;
            #pragma unroll
            for (int off = 16; off; off >>= 1) {
                float ov = __shfl_xor_sync(0xffffffffu, bv, off);
                int   oi = __shfl_xor_sync(0xffffffffu, bi, off);
                if (ov > bv || (ov == bv && oi < bi)) { bv = ov; bi = oi; }
            }
            sel_val[k] = bv; sel_idx[k] = bi;
            if (lane == bi) cur = -1e30f;
        }
        // softmax over the 4 (descending, sel_val[0] is max)
        float m = sel_val[0];
        float ex[TOPK]; float sum = 0.f;
        #pragma unroll
        for (int k = 0; k < TOPK; k++) { ex[k] = expf(sel_val[k] - m); sum += ex[k]; }
        float inv = 1.f / sum;

        float sc = 0.f;
        #pragma unroll
        for (int k = 0; k < TOPK; k++) if (lane == sel_idx[k]) sc = ex[k] * inv;
        scores_out[(size_t)t * NE + lane] = sc;

        if (lane < TOPK) {
            g_topk_idx[t * TOPK + lane] = sel_idx[lane];
            g_topk_w[t * TOPK + lane]   = ex[lane] * inv;
            atomicAdd(&g_count[sel_idx[lane]], 1);
        }
    }
}

// -------- K2: prefix sum (serial, tiny) --------
__global__ void prefix_kernel() {
    if (threadIdx.x == 0) {
        int acc = 0;
        for (int e = 0; e < NE; e++) {
            g_offset[e] = acc;
            g_cursor[e] = acc;
            acc += g_count[e];
        }
    }
}

// -------- K3: scatter tokens into per-expert groups --------
__global__ void scatter_kernel() {
    int t = blockIdx.x * blockDim.x + threadIdx.x;
    if (t >= TOK) return;
    #pragma unroll
    for (int k = 0; k < TOPK; k++) {
        int e   = g_topk_idx[t * TOPK + k];
        int pos = atomicAdd(&g_cursor[e], 1);
        g_pair_token[pos] = t;
        g_pair_e[pos]     = e;
        g_pair_of[t * TOPK + k] = pos;
    }
}

// -------- K4: grouped SGEMM  C = gather(X) @ gate_up[e]  (128x128x8) --------
__global__ __launch_bounds__(256) void gemm1_kernel(const float* __restrict__ x,
                                                    const float* __restrict__ W) {
    const int bx = blockIdx.x;          // col tile 0..15 over 2048
    const int e  = blockIdx.y >> 4;
    const int rt = blockIdx.y & 15;
    const int base = g_offset[e];
    const int cnt  = g_count[e];
    const int row0 = rt * 128;
    if (row0 >= cnt) return;

    __shared__ float As[8][128];
    __shared__ float Bs[8][128];

    const int tid = threadIdx.x;
    const int am = tid >> 1, ak = (tid & 1) * 4;
    int ar = row0 + am; if (ar >= cnt) ar = cnt - 1;
    const float* Arow = x + (size_t)g_pair_token[base + ar] * HD + ak;
    const int bk = tid >> 5, bn = (tid & 31) * 4;
    const float* Bp = W + (size_t)e * HD * TWOI + (size_t)bk * TWOI + bx * 128 + bn;

    const int tx = tid & 15, ty = tid >> 4;
    float acc[8][8];
    #pragma unroll
    for (int i = 0; i < 8; i++)
        #pragma unroll
        for (int j = 0; j < 8; j++) acc[i][j] = 0.f;

    for (int k0 = 0; k0 < HD; k0 += 8) {
        float4 a4 = *(const float4*)(Arow + k0);
        float4 b4 = *(const float4*)(Bp + (size_t)k0 * TWOI);
        As[ak + 0][am] = a4.x; As[ak + 1][am] = a4.y;
        As[ak + 2][am] = a4.z; As[ak + 3][am] = a4.w;
        *(float4*)&Bs[bk][bn] = b4;
        __syncthreads();
        #pragma unroll
        for (int k = 0; k < 8; k++) {
            float a[8], b[8];
            *(float4*)(a)     = *(const float4*)&As[k][ty * 4];
            *(float4*)(a + 4) = *(const float4*)&As[k][64 + ty * 4];
            *(float4*)(b)     = *(const float4*)&Bs[k][tx * 4];
            *(float4*)(b + 4) = *(const float4*)&Bs[k][64 + tx * 4];
            #pragma unroll
            for (int i = 0; i < 8; i++)
                #pragma unroll
                for (int j = 0; j < 8; j++)
                    acc[i][j] += a[i] * b[j];
        }
        __syncthreads();
    }

    #pragma unroll
    for (int i = 0; i < 8; i++) {
        int m = (i < 4) ? (ty * 4 + i) : (64 + ty * 4 + (i - 4));
        int row = row0 + m;
        if (row < cnt) {
            float* out = g_C + (size_t)(base + row) * TWOI + bx * 128;
            *(float4*)(out + tx * 4)      = make_float4(acc[i][0], acc[i][1], acc[i][2], acc[i][3]);
            *(float4*)(out + 64 + tx * 4) = make_float4(acc[i][4], acc[i][5], acc[i][6], acc[i][7]);
        }
    }
}

// -------- K5: bias + clip + GLU activation --------
__global__ void act_kernel(const float* __restrict__ gub) {
    size_t idx = (size_t)blockIdx.x * blockDim.x + threadIdx.x;
    if (idx >= (size_t)PAIRS * ID) return;
    int p = (int)(idx >> 10);
    int i = (int)(idx & 1023);
    int e = g_pair_e[p];
    float gate = g_C[(size_t)p * TWOI + 2 * i]     + gub[(size_t)e * TWOI + 2 * i];
    float up   = g_C[(size_t)p * TWOI + 2 * i + 1] + gub[(size_t)e * TWOI + 2 * i + 1];
    gate = fminf(gate, LIMITF);
    up   = fminf(fmaxf(up, -LIMITF), LIMITF);
    float glu = gate / (1.f + expf(-gate * ALPHAF));
    g_act[(size_t)p * ID + i] = (up + 1.f) * glu;
}

// -------- K6: grouped SGEMM  y = act @ down[e]  (128x128x8) --------
__global__ __launch_bounds__(256) void gemm2_kernel(const float* __restrict__ W) {
    const int bx = blockIdx.x;          // col tile 0..7 over 1024
    const int e  = blockIdx.y >> 4;
    const int rt = blockIdx.y & 15;
    const int base = g_offset[e];
    const int cnt  = g_count[e];
    const int row0 = rt * 128;
    if (row0 >= cnt) return;

    __shared__ float As[8][128];
    __shared__ float Bs[8][128];

    const int tid = threadIdx.x;
    const int am = tid >> 1, ak = (tid & 1) * 4;
    int ar = row0 + am; if (ar >= cnt) ar = cnt - 1;
    const float* Arow = g_act + (size_t)(base + ar) * ID + ak;
    const int bk = tid >> 5, bn = (tid & 31) * 4;
    const float* Bp = W + (size_t)e * ID * HD + (size_t)bk * HD + bx * 128 + bn;

    const int tx = tid & 15, ty = tid >> 4;
    float acc[8][8];
    #pragma unroll
    for (int i = 0; i < 8; i++)
        #pragma unroll
        for (int j = 0; j < 8; j++) acc[i][j] = 0.f;

    for (int k0 = 0; k0 < ID; k0 += 8) {
        float4 a4 = *(const float4*)(Arow + k0);
        float4 b4 = *(const float4*)(Bp + (size_t)k0 * HD);
        As[ak + 0][am] = a4.x; As[ak + 1][am] = a4.y;
        As[ak + 2][am] = a4.z; As[ak + 3][am] = a4.w;
        *(float4*)&Bs[bk][bn] = b4;
        __syncthreads();
        #pragma unroll
        for (int k = 0; k < 8; k++) {
            float a[8], b[8];
            *(float4*)(a)     = *(const float4*)&As[k][ty * 4];
            *(float4*)(a + 4) = *(const float4*)&As[k][64 + ty * 4];
            *(float4*)(b)     = *(const float4*)&Bs[k][tx * 4];
            *(float4*)(b + 4) = *(const float4*)&Bs[k][64 + tx * 4];
            #pragma unroll
            for (int i = 0; i < 8; i++)
                #pragma unroll
                for (int j = 0; j < 8; j++)
                    acc[i][j] += a[i] * b[j];
        }
        __syncthreads();
    }

    #pragma unroll
    for (int i = 0; i < 8; i++) {
        int m = (i < 4) ? (ty * 4 + i) : (64 + ty * 4 + (i - 4));
        int row = row0 + m;
        if (row < cnt) {
            float* out = g_y + (size_t)(base + row) * HD + bx * 128;
            *(float4*)(out + tx * 4)      = make_float4(acc[i][0], acc[i][1], acc[i][2], acc[i][3]);
            *(float4*)(out + 64 + tx * 4) = make_float4(acc[i][4], acc[i][5], acc[i][6], acc[i][7]);
        }
    }
}

// -------- K7: weighted combine + down bias --------
__global__ void combine_kernel(const float* __restrict__ db,
                               float* __restrict__ out) {
    size_t idx = (size_t)blockIdx.x * blockDim.x + threadIdx.x;
    if (idx >= (size_t)TOK * HD) return;
    int t = (int)(idx >> 10);
    int h = (int)(idx & 1023);
    float s = 0.f;
    #pragma unroll
    for (int k = 0; k < TOPK; k++) {
        int   p = g_pair_of[t * TOPK + k];
        int   e = g_topk_idx[t * TOPK + k];
        float w = g_topk_w[t * TOPK + k];
        s += w * (g_y[(size_t)p * HD + h] + db[(size_t)e * HD + h]);
    }
    out[(size_t)t * HD + h] = s;
}

// -------- launch --------
extern "C" void kernel_launch(void* const* d_in, const int* in_sizes, int n_in,
                              void* d_out, int out_size) {
    const float* hidden    = (const float*)d_in[0];   // (2,1024,1024)
    const float* gate_up   = (const float*)d_in[1];   // (32,1024,2048)
    const float* gub       = (const float*)d_in[2];   // (32,2048)
    const float* down      = (const float*)d_in[3];   // (32,1024,1024)
    const float* db        = (const float*)d_in[4];   // (32,1024)
    const float* rw        = (const float*)d_in[5];   // (32,1024)
    const float* rb        = (const float*)d_in[6];   // (32,)

    float* out_routed = (float*)d_out;                        // TOK*HD floats
    float* out_scores = (float*)d_out + (size_t)TOK * HD;     // TOK*NE floats

    reset_kernel<<<1, 32>>>();
    router_kernel<<<TOK, 256>>>(hidden, rw, rb, out_scores);
    prefix_kernel<<<1, 32>>>();
    scatter_kernel<<<(TOK + 255) / 256, 256>>>();

    gemm1_kernel<<<dim3(16, NE * 16), 256>>>(hidden, gate_up);
    act_kernel<<<((size_t)PAIRS * ID + 255) / 256, 256>>>(gub);
    gemm2_kernel<<<dim3(8, NE * 16), 256>>>(down);
    combine_kernel<<<((size_t)TOK * HD + 255) / 256, 256>>>(db, out_routed);
}

// round 2
// speedup vs baseline: 3.9737x; 3.9737x over previous
#include <cuda_runtime.h>
#include <math.h>

// Problem constants
#define TOK   2048
#define HD    1024
#define ID    1024
#define NE    32
#define TOPK  4
#define TWOI  2048
#define PAIRS (TOK*TOPK)
#define LIMITF 7.0f
#define ALPHAF 1.702f

// -------- device scratch --------
__device__ int   g_count[NE];
__device__ int   g_offset[NE];
__device__ int   g_cursor[NE];
__device__ int   g_topk_idx[TOK * TOPK];
__device__ float g_topk_w[TOK * TOPK];
__device__ int   g_pair_token[PAIRS];
__device__ int   g_pair_of[TOK * TOPK];
__device__ float g_act[(size_t)PAIRS * ID];   // activated intermediate (32 MB)
__device__ float g_y[(size_t)PAIRS * HD];     // down GEMM output (32 MB)

// -------- helpers --------
__device__ __forceinline__ unsigned f2tf(float x) {
    unsigned r;
    asm("cvt.rna.tf32.f32 %0, %1;" : "=r"(r) : "f"(x));
    return r;
}

__device__ __forceinline__ void mma_tf32(float* d, const unsigned* a, const unsigned* b) {
    asm volatile(
        "mma.sync.aligned.m16n8k8.row.col.f32.tf32.tf32.f32 "
        "{%0,%1,%2,%3}, {%4,%5,%6,%7}, {%8,%9}, {%0,%1,%2,%3};\n"
        : "+f"(d[0]), "+f"(d[1]), "+f"(d[2]), "+f"(d[3])
        : "r"(a[0]), "r"(a[1]), "r"(a[2]), "r"(a[3]),
          "r"(b[0]), "r"(b[1]));
}

__device__ __forceinline__ void cp16(void* s, const void* g) {
    unsigned sa = (unsigned)__cvta_generic_to_shared(s);
    asm volatile("cp.async.cg.shared.global [%0], [%1], 16;\n" :: "r"(sa), "l"(g));
}
#define CP_COMMIT() asm volatile("cp.async.commit_group;\n" ::: "memory")
#define CP_WAIT0()  asm volatile("cp.async.wait_group 0;\n" ::: "memory")

// -------- K0: reset counters --------
__global__ void reset_kernel() {
    int i = threadIdx.x;
    if (i < NE) g_count[i] = 0;
}

// -------- K1: router --------
__global__ void router_kernel(const float* __restrict__ x,
                              const float* __restrict__ rw,
                              const float* __restrict__ rb,
                              float* __restrict__ scores_out) {
    const int t    = blockIdx.x;
    const int tid  = threadIdx.x;
    const int warp = tid >> 5;
    const int lane = tid & 31;

    __shared__ float logits[NE];
    const float* xr = x + (size_t)t * HD;

    for (int e = warp; e < NE; e += 8) {
        const float* w = rw + (size_t)e * HD;
        float s = 0.f;
        for (int h = lane; h < HD; h += 32) s += xr[h] * w[h];
        #pragma unroll
        for (int off = 16; off; off >>= 1) s += __shfl_down_sync(0xffffffffu, s, off);
        if (lane == 0) logits[e] = s + rb[e];
    }
    __syncthreads();

    if (warp == 0) {
        float cur = logits[lane];
        float sel_val[TOPK];
        int   sel_idx[TOPK];
        #pragma unroll
        for (int k = 0; k < TOPK; k++) {
            float bv = cur; int bi = lane;
            #pragma unroll
            for (int off = 16; off; off >>= 1) {
                float ov = __shfl_xor_sync(0xffffffffu, bv, off);
                int   oi = __shfl_xor_sync(0xffffffffu, bi, off);
                if (ov > bv || (ov == bv && oi < bi)) { bv = ov; bi = oi; }
            }
            sel_val[k] = bv; sel_idx[k] = bi;
            if (lane == bi) cur = -1e30f;
        }
        float m = sel_val[0];
        float ex[TOPK]; float sum = 0.f;
        #pragma unroll
        for (int k = 0; k < TOPK; k++) { ex[k] = expf(sel_val[k] - m); sum += ex[k]; }
        float inv = 1.f / sum;

        float sc = 0.f;
        #pragma unroll
        for (int k = 0; k < TOPK; k++) if (lane == sel_idx[k]) sc = ex[k] * inv;
        scores_out[(size_t)t * NE + lane] = sc;

        if (lane < TOPK) {
            g_topk_idx[t * TOPK + lane] = sel_idx[lane];
            g_topk_w[t * TOPK + lane]   = ex[lane] * inv;
            atomicAdd(&g_count[sel_idx[lane]], 1);
        }
    }
}

// -------- K2: prefix sum --------
__global__ void prefix_kernel() {
    if (threadIdx.x == 0) {
        int acc = 0;
        for (int e = 0; e < NE; e++) {
            g_offset[e] = acc;
            g_cursor[e] = acc;
            acc += g_count[e];
        }
    }
}

// -------- K3: scatter --------
__global__ void scatter_kernel() {
    int t = blockIdx.x * blockDim.x + threadIdx.x;
    if (t >= TOK) return;
    #pragma unroll
    for (int k = 0; k < TOPK; k++) {
        int e   = g_topk_idx[t * TOPK + k];
        int pos = atomicAdd(&g_cursor[e], 1);
        g_pair_token[pos] = t;
        g_pair_of[t * TOPK + k] = pos;
    }
}

// -------- K4: tf32 grouped GEMM #1 + fused activation epilogue --------
// C(row, :) = gather(X) @ gate_up[e]; 128x128 tile, BK=16, act fused.
__global__ __launch_bounds__(256, 2) void gemm1_kernel(const float* __restrict__ x,
                                                       const float* __restrict__ W,
                                                       const float* __restrict__ gub) {
    const int bx = blockIdx.x;            // 0..15 over 2048 cols
    const int e  = blockIdx.y >> 4;
    const int rt = blockIdx.y & 15;
    const int base = g_offset[e];
    const int cnt  = g_count[e];
    const int row0 = rt * 128;
    if (row0 >= cnt) return;

    __shared__ float As[2][128][20];      // [m][k] layout, pad 4
    __shared__ float Bs[2][16][132];      // [k][n] layout, pad 4

    const int tid  = threadIdx.x;
    const int lane = tid & 31;
    const int wid  = tid >> 5;
    const int wm   = wid >> 2;            // 0..1
    const int wn   = wid & 3;             // 0..3
    const int lr   = lane >> 2;           // 0..7
    const int lc   = lane & 3;            // 0..3

    // A loader: one gathered row per thread, 2x16B along k
    const int ar = tid >> 1;
    int asrc = row0 + ar; if (asrc >= cnt) asrc = cnt - 1;
    const float* aptr = x + (size_t)g_pair_token[base + asrc] * HD + (tid & 1) * 8;
    const int ak = (tid & 1) * 8;
    // B loader: k-row tid>>5 (and +8), 16B along n
    const float* bptr = W + (size_t)e * HD * TWOI + (size_t)(tid >> 5) * TWOI
                        + bx * 128 + (tid & 31) * 4;
    const int bkr = tid >> 5, bnc = (tid & 31) * 4;

    // prologue: tile 0 -> buf 0
    cp16(&As[0][ar][ak],     aptr);
    cp16(&As[0][ar][ak + 4], aptr + 4);
    cp16(&Bs[0][bkr][bnc],     bptr);
    cp16(&Bs[0][bkr + 8][bnc], bptr + (size_t)8 * TWOI);
    CP_COMMIT();

    float acc[4][4][4];
    #pragma unroll
    for (int i = 0; i < 4; i++)
        #pragma unroll
        for (int j = 0; j < 4; j++)
            #pragma unroll
            for (int q = 0; q < 4; q++) acc[i][j][q] = 0.f;

    const int NK = HD / 16;   // 64
    for (int kt = 0; kt < NK; kt++) {
        CP_WAIT0();
        __syncthreads();
        const int cur = kt & 1;
        if (kt + 1 < NK) {
            const int nb = cur ^ 1;
            const float* ag = aptr + (kt + 1) * 16;
            cp16(&As[nb][ar][ak],     ag);
            cp16(&As[nb][ar][ak + 4], ag + 4);
            const float* bg = bptr + (size_t)(kt + 1) * 16 * TWOI;
            cp16(&Bs[nb][bkr][bnc],     bg);
            cp16(&Bs[nb][bkr + 8][bnc], bg + (size_t)8 * TWOI);
            CP_COMMIT();
        }
        #pragma unroll
        for (int kk = 0; kk < 2; kk++) {
            unsigned af[4][4];
            #pragma unroll
            for (int mt = 0; mt < 4; mt++) {
                const int r = wm * 64 + mt * 16 + lr;
                const int k = kk * 8 + lc;
                af[mt][0] = f2tf(As[cur][r][k]);
                af[mt][1] = f2tf(As[cur][r + 8][k]);
                af[mt][2] = f2tf(As[cur][r][k + 4]);
                af[mt][3] = f2tf(As[cur][r + 8][k + 4]);
            }
            unsigned bf[4][2];
            #pragma unroll
            for (int nt = 0; nt < 4; nt++) {
                const int n = wn * 32 + nt * 8 + lr;
                bf[nt][0] = f2tf(Bs[cur][kk * 8 + lc][n]);
                bf[nt][1] = f2tf(Bs[cur][kk * 8 + lc + 4][n]);
            }
            #pragma unroll
            for (int mt = 0; mt < 4; mt++)
                #pragma unroll
                for (int nt = 0; nt < 4; nt++)
                    mma_tf32(acc[mt][nt], af[mt], bf[nt]);
        }
        __syncthreads();
    }

    // fused activation epilogue: each thread holds (gate, up) column pairs
    const float* gb = gub + (size_t)e * TWOI;
    #pragma unroll
    for (int mt = 0; mt < 4; mt++) {
        #pragma unroll
        for (int half = 0; half < 2; half++) {
            const int r = row0 + wm * 64 + mt * 16 + lr + half * 8;
            if (r < cnt) {
                float* orow = g_act + (size_t)(base + r) * ID;
                #pragma unroll
                for (int nt = 0; nt < 4; nt++) {
                    const int i = bx * 64 + wn * 16 + nt * 4 + lc;
                    float gate = acc[mt][nt][half * 2 + 0] + gb[2 * i];
                    float up   = acc[mt][nt][half * 2 + 1] + gb[2 * i + 1];
                    gate = fminf(gate, LIMITF);
                    up   = fminf(fmaxf(up, -LIMITF), LIMITF);
                    float glu = gate / (1.f + __expf(-gate * ALPHAF));
                    orow[i] = (up + 1.f) * glu;
                }
            }
        }
    }
}

// -------- K6: tf32 grouped GEMM #2 (act @ down[e]) --------
__global__ __launch_bounds__(256, 2) void gemm2_kernel(const float* __restrict__ W) {
    const int bx = blockIdx.x;            // 0..7 over 1024 cols
    const int e  = blockIdx.y >> 4;
    const int rt = blockIdx.y & 15;
    const int base = g_offset[e];
    const int cnt  = g_count[e];
    const int row0 = rt * 128;
    if (row0 >= cnt) return;

    __shared__ float As[2][128][20];
    __shared__ float Bs[2][16][132];

    const int tid  = threadIdx.x;
    const int lane = tid & 31;
    const int wid  = tid >> 5;
    const int wm   = wid >> 2;
    const int wn   = wid & 3;
    const int lr   = lane >> 2;
    const int lc   = lane & 3;

    const int ar = tid >> 1;
    int asrc = row0 + ar; if (asrc >= cnt) asrc = cnt - 1;
    const float* aptr = g_act + (size_t)(base + asrc) * ID + (tid & 1) * 8;
    const int ak = (tid & 1) * 8;
    const float* bptr = W + (size_t)e * ID * HD + (size_t)(tid >> 5) * HD
                        + bx * 128 + (tid & 31) * 4;
    const int bkr = tid >> 5, bnc = (tid & 31) * 4;

    cp16(&As[0][ar][ak],     aptr);
    cp16(&As[0][ar][ak + 4], aptr + 4);
    cp16(&Bs[0][bkr][bnc],     bptr);
    cp16(&Bs[0][bkr + 8][bnc], bptr + (size_t)8 * HD);
    CP_COMMIT();

    float acc[4][4][4];
    #pragma unroll
    for (int i = 0; i < 4; i++)
        #pragma unroll
        for (int j = 0; j < 4; j++)
            #pragma unroll
            for (int q = 0; q < 4; q++) acc[i][j][q] = 0.f;

    const int NK = ID / 16;
    for (int kt = 0; kt < NK; kt++) {
        CP_WAIT0();
        __syncthreads();
        const int cur = kt & 1;
        if (kt + 1 < NK) {
            const int nb = cur ^ 1;
            const float* ag = aptr + (kt + 1) * 16;
            cp16(&As[nb][ar][ak],     ag);
            cp16(&As[nb][ar][ak + 4], ag + 4);
            const float* bg = bptr + (size_t)(kt + 1) * 16 * HD;
            cp16(&Bs[nb][bkr][bnc],     bg);
            cp16(&Bs[nb][bkr + 8][bnc], bg + (size_t)8 * HD);
            CP_COMMIT();
        }
        #pragma unroll
        for (int kk = 0; kk < 2; kk++) {
            unsigned af[4][4];
            #pragma unroll
            for (int mt = 0; mt < 4; mt++) {
                const int r = wm * 64 + mt * 16 + lr;
                const int k = kk * 8 + lc;
                af[mt][0] = f2tf(As[cur][r][k]);
                af[mt][1] = f2tf(As[cur][r + 8][k]);
                af[mt][2] = f2tf(As[cur][r][k + 4]);
                af[mt][3] = f2tf(As[cur][r + 8][k + 4]);
            }
            unsigned bf[4][2];
            #pragma unroll
            for (int nt = 0; nt < 4; nt++) {
                const int n = wn * 32 + nt * 8 + lr;
                bf[nt][0] = f2tf(Bs[cur][kk * 8 + lc][n]);
                bf[nt][1] = f2tf(Bs[cur][kk * 8 + lc + 4][n]);
            }
            #pragma unroll
            for (int mt = 0; mt < 4; mt++)
                #pragma unroll
                for (int nt = 0; nt < 4; nt++)
                    mma_tf32(acc[mt][nt], af[mt], bf[nt]);
        }
        __syncthreads();
    }

    #pragma unroll
    for (int mt = 0; mt < 4; mt++) {
        #pragma unroll
        for (int half = 0; half < 2; half++) {
            const int r = row0 + wm * 64 + mt * 16 + lr + half * 8;
            if (r < cnt) {
                float* orow = g_y + (size_t)(base + r) * HD;
                #pragma unroll
                for (int nt = 0; nt < 4; nt++) {
                    const int c = bx * 128 + wn * 32 + nt * 8 + lc * 2;
                    float2 v = make_float2(acc[mt][nt][half * 2 + 0],
                                           acc[mt][nt][half * 2 + 1]);
                    *(float2*)(orow + c) = v;
                }
            }
        }
    }
}

// -------- K7: weighted combine + down bias --------
__global__ void combine_kernel(const float* __restrict__ db,
                               float* __restrict__ out) {
    size_t idx = (size_t)blockIdx.x * blockDim.x + threadIdx.x;
    if (idx >= (size_t)TOK * HD) return;
    int t = (int)(idx >> 10);
    int h = (int)(idx & 1023);
    float s = 0.f;
    #pragma unroll
    for (int k = 0; k < TOPK; k++) {
        int   p = g_pair_of[t * TOPK + k];
        int   e = g_topk_idx[t * TOPK + k];
        float w = g_topk_w[t * TOPK + k];
        s += w * (g_y[(size_t)p * HD + h] + db[(size_t)e * HD + h]);
    }
    out[(size_t)t * HD + h] = s;
}

// -------- launch --------
extern "C" void kernel_launch(void* const* d_in, const int* in_sizes, int n_in,
                              void* d_out, int out_size) {
    const float* hidden  = (const float*)d_in[0];
    const float* gate_up = (const float*)d_in[1];
    const float* gub     = (const float*)d_in[2];
    const float* down    = (const float*)d_in[3];
    const float* db      = (const float*)d_in[4];
    const float* rw      = (const float*)d_in[5];
    const float* rb      = (const float*)d_in[6];

    float* out_routed = (float*)d_out;
    float* out_scores = (float*)d_out + (size_t)TOK * HD;

    reset_kernel<<<1, 32>>>();
    router_kernel<<<TOK, 256>>>(hidden, rw, rb, out_scores);
    prefix_kernel<<<1, 32>>>();
    scatter_kernel<<<(TOK + 255) / 256, 256>>>();

    gemm1_kernel<<<dim3(16, NE * 16), 256>>>(hidden, gate_up, gub);
    gemm2_kernel<<<dim3(8, NE * 16), 256>>>(down);
    combine_kernel<<<((size_t)TOK * HD + 255) / 256, 256>>>(db, out_routed);
}